// round 15
// baseline (speedup 1.0000x reference)
#include <cuda_runtime.h>
#include <cuda_fp16.h>
#include <cuda_bf16.h>
#include <mma.h>
#include <cstdint>

using namespace nvcuda;

#define N_USERS  100000
#define N_ITEMS  100000
#define N_FEAT   256
#define BATCH    8192
#define CLASSES  5
#define EDGES    500000
#define D_CONV   128
#define D_EMB    256
#define SEGS     10
#define BN_EPS   1e-3f

#define ASTRIDE_H 24   // A smem row stride in halves
#define BSTRIDE_H 136  // B smem row stride in halves
#define CSTRIDE   20   // staging row stride (floats)

// ---------------- scratch ----------------------------------------------------
__device__ int    g_cnt [SEGS * BATCH];   // zeroed by decode_kernel tail (and at load)
__device__ int    g_off [SEGS * BATCH];
__device__ int2   g_ep  [SEGS * EDGES];
__device__ __half g_u16 [(long)N_USERS * N_FEAT];
__device__ __half g_i16 [(long)N_ITEMS * N_FEAT];
__device__ float  g_agg [SEGS * BATCH * N_FEAT];
__device__ float  g_f   [2 * BATCH * N_FEAT];
__device__ float  g_h   [2 * BATCH * CLASSES * D_CONV];
__device__ float  g_emb [2 * BATCH * D_EMB];
__device__ float  g_t   [2 * BATCH * D_EMB];

#define EQUARTER   (SEGS * EDGES / 4)            // 1,250,000
#define HISTBLK    ((EQUARTER + 255) / 256)      // 4883
#define FP16QUADS  (2L * N_USERS * N_FEAT / 4)   // 12.8M
#define FP16BLK    ((int)((FP16QUADS + 255) / 256))

// ---------------- prep: hist (blocks [0,HISTBLK)) + tofp16 (rest) -----------
__global__ void prep_kernel(const float* __restrict__ udst_uf, // alias naming below
                            const int* __restrict__ udst, const int* __restrict__ idst,
                            const float* __restrict__ uf, const float* __restrict__ itf) {
    int b = blockIdx.x;
    if (b < HISTBLK) {
        int i = b * 256 + threadIdx.x;
        if (i >= EQUARTER) return;
#pragma unroll
        for (int j = 0; j < 4; j++) {
            int idx = i + j * EQUARTER;
            int seg = idx / EDGES, e = idx - seg * EDGES;
            int dst = (seg < CLASSES) ? udst[seg * EDGES + e]
                                      : idst[(seg - CLASSES) * EDGES + e];
            atomicAdd(&g_cnt[seg * BATCH + dst], 1);
        }
    } else {
        long i = (long)(b - HISTBLK) * 256 + threadIdx.x;
        const long Q = (long)N_USERS * N_FEAT / 4;
        if (i < Q) {
            float4 v = ((const float4*)uf)[i];
            __half2* o = (__half2*)g_u16;
            o[i * 2]     = __floats2half2_rn(v.x, v.y);
            o[i * 2 + 1] = __floats2half2_rn(v.z, v.w);
        } else if (i < 2 * Q) {
            long j = i - Q;
            float4 v = ((const float4*)itf)[j];
            __half2* o = (__half2*)g_i16;
            o[j * 2]     = __floats2half2_rn(v.x, v.y);
            o[j * 2 + 1] = __floats2half2_rn(v.z, v.w);
        }
    }
}

__global__ void scan_kernel() {
    int seg = blockIdx.x;
    int t = threadIdx.x;
    int base = seg * BATCH + t * 8;
    int v[8], s = 0;
#pragma unroll
    for (int j = 0; j < 8; j++) { v[j] = g_cnt[base + j]; s += v[j]; }
    __shared__ int sh[1024];
    sh[t] = s;
    __syncthreads();
    for (int off = 1; off < 1024; off <<= 1) {
        int x = (t >= off) ? sh[t - off] : 0;
        __syncthreads();
        sh[t] += x;
        __syncthreads();
    }
    int run = sh[t] - s;
#pragma unroll
    for (int j = 0; j < 8; j++) {
        g_off[base + j] = run;
        g_cnt[base + j] = run;
        run += v[j];
    }
}

__global__ void scatter_kernel(const int* __restrict__ usrc, const int* __restrict__ udst,
                               const float* __restrict__ uw,
                               const int* __restrict__ isrc, const int* __restrict__ idst,
                               const float* __restrict__ iw) {
    int i = blockIdx.x * 256 + threadIdx.x;
    if (i >= EQUARTER) return;
#pragma unroll
    for (int j = 0; j < 4; j++) {
        int idx = i + j * EQUARTER;
        int seg = idx / EDGES, e = idx - seg * EDGES;
        int src, dst; float w;
        if (seg < CLASSES) {
            int o = seg * EDGES + e;
            src = usrc[o]; dst = udst[o]; w = uw[o];
        } else {
            int o = (seg - CLASSES) * EDGES + e;
            src = isrc[o]; dst = idst[o]; w = iw[o];
        }
        int pos = atomicAdd(&g_cnt[seg * BATCH + dst], 1);
        g_ep[seg * EDGES + pos] = make_int2(src, __float_as_int(w));
    }
}

// ---------------- fp16 WMMA GEMM core: 128 threads, 128x128 tile ------------
// EPI: 0 = none (direct), 1 = bias+BN+relu, 2 = BN+relu, 3 = relu (direct)
template<int EPI>
__device__ __forceinline__ void gemm_core128(
    __half (*As)[128][ASTRIDE_H], __half (*Bs)[16][BSTRIDE_H],
    float (*stage)[16][CSTRIDE],
    int bx, int by,
    const float* __restrict__ A1, const float* __restrict__ A2,
    int lda1, int lda2, int ksplit, const int* __restrict__ gidx,
    const float* __restrict__ B1, const float* __restrict__ B2, int ldb,
    float* __restrict__ C, int ldc, int col0, int K,
    const float* __restrict__ bias, const float* __restrict__ bnp, int bn_dim)
{
    const int tid = threadIdx.x;
    const int m0 = by * 128, n0 = bx * 128;
    const int warp = tid >> 5, lane = tid & 31;
    const int wm0 = (warp & 1) * 64, wn0 = (warp >> 1) * 64;

    const int arow = tid;
    const int brow = tid >> 3, bcol = (tid & 7) * 16;

    const float *Ap1, *Ap2 = nullptr;
    {
        int r = gidx ? gidx[m0 + arow] : (m0 + arow);
        Ap1 = A1 + (long)r * lda1;
        if (A2) Ap2 = A2 + (long)r * lda2;
    }
    const float* Bp1 = B1 + n0 + bcol;
    const float* Bp2 = B2 ? (B2 + n0 + bcol) : nullptr;

    wmma::fragment<wmma::accumulator, 16, 16, 16, float> facc[4][4];
#pragma unroll
    for (int i = 0; i < 4; i++)
#pragma unroll
        for (int j = 0; j < 4; j++) wmma::fill_fragment(facc[i][j], 0.f);

    float a_st[16], b_st[16];

    auto load_chunk = [&](int k0) {
        const float *ap, *bp;
        if (k0 < ksplit) {
            ap = Ap1 + k0;
            bp = Bp1 + (long)(k0 + brow) * ldb;
        } else {
            ap = Ap2 + (k0 - ksplit);
            bp = Bp2 + (long)(k0 - ksplit + brow) * ldb;
        }
#pragma unroll
        for (int q = 0; q < 4; q++) {
            float4 x = *(const float4*)(ap + q * 4);
            a_st[q * 4 + 0] = x.x; a_st[q * 4 + 1] = x.y;
            a_st[q * 4 + 2] = x.z; a_st[q * 4 + 3] = x.w;
        }
#pragma unroll
        for (int q = 0; q < 4; q++) {
            float4 u = *(const float4*)(bp + q * 4);
            b_st[q * 4 + 0] = u.x; b_st[q * 4 + 1] = u.y;
            b_st[q * 4 + 2] = u.z; b_st[q * 4 + 3] = u.w;
        }
    };

    auto store_chunk = [&](int buf) {
        __half2 ha[8];
#pragma unroll
        for (int q = 0; q < 8; q++)
            ha[q] = __floats2half2_rn(a_st[q * 2], a_st[q * 2 + 1]);
        *(uint4*)&As[buf][arow][0] = *(uint4*)&ha[0];
        *(uint4*)&As[buf][arow][8] = *(uint4*)&ha[4];
        __half2 hb[8];
#pragma unroll
        for (int q = 0; q < 8; q++)
            hb[q] = __floats2half2_rn(b_st[q * 2], b_st[q * 2 + 1]);
        *(uint4*)&Bs[buf][brow][bcol]     = *(uint4*)&hb[0];
        *(uint4*)&Bs[buf][brow][bcol + 8] = *(uint4*)&hb[4];
    };

    const int nc = K / 16;
    load_chunk(0);
    store_chunk(0);
    __syncthreads();

    for (int ch = 0; ch < nc; ch++) {
        int cur = ch & 1;
        if (ch + 1 < nc) load_chunk((ch + 1) * 16);
        wmma::fragment<wmma::matrix_b, 16, 16, 16, __half, wmma::row_major> fb[4];
#pragma unroll
        for (int na = 0; na < 4; na++)
            wmma::load_matrix_sync(fb[na], &Bs[cur][0][wn0 + na * 16], BSTRIDE_H);
#pragma unroll
        for (int ma = 0; ma < 4; ma++) {
            wmma::fragment<wmma::matrix_a, 16, 16, 16, __half, wmma::row_major> fa;
            wmma::load_matrix_sync(fa, &As[cur][wm0 + ma * 16][0], ASTRIDE_H);
#pragma unroll
            for (int na = 0; na < 4; na++)
                wmma::mma_sync(facc[ma][na], fa, fb[na], facc[ma][na]);
        }
        if (ch + 1 < nc) {
            store_chunk(cur ^ 1);
            __syncthreads();
        }
    }

    if (EPI == 0 || EPI == 3) {
#pragma unroll
        for (int ma = 0; ma < 4; ma++)
#pragma unroll
            for (int na = 0; na < 4; na++) {
                if (EPI == 3) {
#pragma unroll
                    for (int e = 0; e < facc[ma][na].num_elements; e++)
                        facc[ma][na].x[e] = fmaxf(facc[ma][na].x[e], 0.f);
                }
                float* cp = C + (long)(m0 + wm0 + ma * 16) * ldc
                              + col0 + n0 + wn0 + na * 16;
                wmma::store_matrix_sync(cp, facc[ma][na], ldc, wmma::mem_row_major);
            }
    } else {
        __syncthreads();
        const int srow = lane >> 1;
        const int scol = (lane & 1) * 8;
#pragma unroll
        for (int ma = 0; ma < 4; ma++) {
#pragma unroll
            for (int na = 0; na < 4; na++) {
                wmma::store_matrix_sync(&stage[warp][0][0], facc[ma][na], CSTRIDE,
                                        wmma::mem_row_major);
                __syncwarp();
                int r  = m0 + wm0 + ma * 16 + srow;
                int cb = n0 + wn0 + na * 16 + scol;
                float x[8];
#pragma unroll
                for (int j = 0; j < 8; j++) {
                    float v = stage[warp][srow][scol + j];
                    int cgl = cb + j;
                    int cg  = col0 + cgl;
                    if (EPI == 1) v += bias[cgl];
                    float gm = bnp[cg];
                    float be = bnp[bn_dim + cg];
                    float mn = bnp[2 * bn_dim + cg];
                    float vr = bnp[3 * bn_dim + cg];
                    v = gm * (v - mn) * rsqrtf(vr + BN_EPS) + be;
                    x[j] = fmaxf(v, 0.f);
                }
                float* cp = C + (long)r * ldc + col0 + cb;
                *(float4*)(cp)     = make_float4(x[0], x[1], x[2], x[3]);
                *(float4*)(cp + 4) = make_float4(x[4], x[5], x[6], x[7]);
                __syncwarp();
            }
        }
    }
}

// sizes for smem aliasing
#define GEMM_SMEM (2*128*ASTRIDE_H*2 + 2*16*BSTRIDE_H*2 + 4*16*CSTRIDE*4)

// ---- merged: agg (y<10) + f projections (y==10, bx<256), 128 threads -------
__global__ void __launch_bounds__(128) aggproj_kernel(
    const float* __restrict__ user_feat, const float* __restrict__ item_feat,
    const int* __restrict__ user_idx, const int* __restrict__ item_idx,
    const float* __restrict__ W_fu, const float* __restrict__ b_fu, const float* __restrict__ bn_fu,
    const float* __restrict__ W_fi, const float* __restrict__ b_fi, const float* __restrict__ bn_fi,
    float* __restrict__ fb)
{
    __shared__ __align__(16) char sm[GEMM_SMEM];
    int y = blockIdx.y;
    if (y < SEGS) {
        // aggregation: 32 lanes x 8 feats, 4 edge slots
        float (*red)[8] = (float(*)[8])sm;     // 128 x 8 floats = 4KB
        int dst = blockIdx.x;
        int seg = y;
        int tid  = threadIdx.x;
        int lane = tid & 31;
        int slot = tid >> 5;
        const uint4* feat = (const uint4*)((seg < CLASSES) ? g_i16 : g_u16);
        int start = g_off[seg * BATCH + dst];
        int end   = g_cnt[seg * BATCH + dst];
        const int2* ep = g_ep + seg * EDGES;

        float acc[8];
#pragma unroll
        for (int j = 0; j < 8; j++) acc[j] = 0.f;

        for (int e = start + slot; e < end; e += 4) {
            int2 p = ep[e];
            float w = __int_as_float(p.y);
            uint4 v = feat[(long)p.x * 32 + lane];
            const __half2* h = (const __half2*)&v;
#pragma unroll
            for (int q = 0; q < 4; q++) {
                float2 f = __half22float2(h[q]);
                acc[q * 2]     += w * f.x;
                acc[q * 2 + 1] += w * f.y;
            }
        }
#pragma unroll
        for (int j = 0; j < 8; j++) red[tid][j] = acc[j];
        __syncthreads();
        if (slot == 0) {
            float s[8];
#pragma unroll
            for (int j = 0; j < 8; j++) s[j] = red[lane][j];
#pragma unroll
            for (int k = 1; k < 4; k++)
#pragma unroll
                for (int j = 0; j < 8; j++) s[j] += red[k * 32 + lane][j];
            float4* outp = (float4*)(g_agg + ((long)seg * BATCH + dst) * N_FEAT + lane * 8);
            outp[0] = make_float4(s[0], s[1], s[2], s[3]);
            outp[1] = make_float4(s[4], s[5], s[6], s[7]);
        }
    } else {
        int b = blockIdx.x;
        if (b >= 256) return;
        int bx = b & 1, by = (b >> 1) & 63, side = b >> 7;
        __half (*As)[128][ASTRIDE_H] = (__half(*)[128][ASTRIDE_H])sm;
        __half (*Bs)[16][BSTRIDE_H]  = (__half(*)[16][BSTRIDE_H])(sm + 2*128*ASTRIDE_H*2);
        float  (*St)[16][CSTRIDE]    = (float(*)[16][CSTRIDE])(sm + 2*128*ASTRIDE_H*2 + 2*16*BSTRIDE_H*2);
        const float* A   = side ? item_feat : user_feat;
        const int*   gx  = side ? item_idx  : user_idx;
        const float* B   = side ? W_fi  : W_fu;
        const float* bi  = side ? b_fi  : b_fu;
        const float* bn  = side ? bn_fi : bn_fu;
        float* C = fb + (long)side * BATCH * 256;
        gemm_core128<1>(As, Bs, St, bx, by, A, nullptr, N_FEAT, 0, 1 << 30, gx,
                        B, nullptr, 256, C, 256, 0, N_FEAT, bi, bn, 256);
    }
}

// ---- class projections: z = seg (0..9) --------------------------------------
__global__ void __launch_bounds__(128) class_proj_kernel(
    const float* __restrict__ agg,
    const float* __restrict__ Wuc, const float* __restrict__ Wic,
    const float* __restrict__ bn_hu, const float* __restrict__ bn_hi,
    float* __restrict__ hb)
{
    __shared__ __half As[2][128][ASTRIDE_H];
    __shared__ __half Bs[2][16][BSTRIDE_H];
    __shared__ float  St[4][16][CSTRIDE];
    int seg = blockIdx.z;
    int side = seg / CLASSES, c = seg % CLASSES;
    const float* A  = agg + (long)seg * BATCH * N_FEAT;
    const float* B  = (side ? Wic : Wuc) + (long)c * N_FEAT * D_CONV;
    const float* bn = side ? bn_hi : bn_hu;
    float* C = hb + (long)side * BATCH * (CLASSES * D_CONV);
    gemm_core128<2>(As, Bs, St, blockIdx.x, blockIdx.y, A, nullptr, N_FEAT, 0, 1 << 30,
                    nullptr, B, nullptr, D_CONV, C, CLASSES * D_CONV, c * D_CONV,
                    N_FEAT, nullptr, bn, CLASSES * D_CONV);
}

// ---- embeddings --------------------------------------------------------------
__global__ void __launch_bounds__(128) emb_kernel(
    const float* __restrict__ fb, const float* __restrict__ hb,
    const float* __restrict__ W2_fu, const float* __restrict__ W2_hu,
    const float* __restrict__ W2_fi, const float* __restrict__ W2_hi,
    float* __restrict__ emb)
{
    __shared__ __half As[2][128][ASTRIDE_H];
    __shared__ __half Bs[2][16][BSTRIDE_H];
    __shared__ float  St[4][16][CSTRIDE];
    const int HD = CLASSES * D_CONV;
    int z = blockIdx.z;
    const float* A1 = fb + (long)z * BATCH * 256;
    const float* A2 = hb + (long)z * BATCH * HD;
    const float* B1 = z ? W2_fi : W2_fu;
    const float* B2 = z ? W2_hi : W2_hu;
    float* C = emb + (long)z * BATCH * D_EMB;
    gemm_core128<3>(As, Bs, St, blockIdx.x, blockIdx.y, A1, A2, 256, HD, 256, nullptr,
                    B1, B2, D_EMB, C, D_EMB, 0, 256 + HD, nullptr, nullptr, 0);
}

// ---- decoder t_k = user_emb @ Wdec[k] ---------------------------------------
__global__ void __launch_bounds__(128) dec_kernel(
    const float* __restrict__ uemb, const float* __restrict__ Wdec,
    float* __restrict__ tdec)
{
    __shared__ __half As[2][128][ASTRIDE_H];
    __shared__ __half Bs[2][16][BSTRIDE_H];
    __shared__ float  St[4][16][CSTRIDE];
    int z = blockIdx.z;
    gemm_core128<0>(As, Bs, St, blockIdx.x, blockIdx.y, uemb, nullptr, D_EMB, 0, 1 << 30,
                    nullptr, Wdec + (long)z * D_EMB * D_EMB, nullptr, D_EMB,
                    tdec + (long)z * BATCH * D_EMB, D_EMB, 0, D_EMB,
                    nullptr, nullptr, 0);
}

// ---------------- bilinear combine + counter re-zero -------------------------
__global__ void decode_kernel(const float* __restrict__ t0, const float* __restrict__ t1,
                              const float* __restrict__ ve, const float* __restrict__ Wcomb,
                              float* __restrict__ out) {
    int b = blockIdx.x, t = threadIdx.x;
    float v  = ve[(long)b * D_EMB + t];
    float a0 = t0[(long)b * D_EMB + t] * v;
    float a1 = t1[(long)b * D_EMB + t] * v;
#pragma unroll
    for (int o = 16; o; o >>= 1) {
        a0 += __shfl_down_sync(0xffffffffu, a0, o);
        a1 += __shfl_down_sync(0xffffffffu, a1, o);
    }
    __shared__ float s0[8], s1[8];
    if ((t & 31) == 0) { s0[t >> 5] = a0; s1[t >> 5] = a1; }
    __syncthreads();
    if (t == 0) {
        float d0 = 0.f, d1 = 0.f;
#pragma unroll
        for (int i = 0; i < 8; i++) { d0 += s0[i]; d1 += s1[i]; }
        s0[0] = d0; s1[0] = d1;
    }
    __syncthreads();
    if (t < CLASSES)
        out[(long)b * CLASSES + t] = Wcomb[t * 2] * s0[0] + Wcomb[t * 2 + 1] * s1[0];
    // re-zero edge counters for the next call/replay (g_cnt is 0 at module load)
    if (t >= 32 && t < 32 + SEGS) g_cnt[(long)b * SEGS + (t - 32)] = 0;
}

// ---------------- launch ----------------------------------------------------
extern "C" void kernel_launch(void* const* d_in, const int* in_sizes, int n_in,
                              void* d_out, int out_size) {
    const float* user_feat = (const float*)d_in[0];
    const float* item_feat = (const float*)d_in[1];
    const int*   user_idx  = (const int*)d_in[2];
    const int*   item_idx  = (const int*)d_in[3];
    const int*   u_src     = (const int*)d_in[4];
    const int*   u_dst     = (const int*)d_in[5];
    const float* u_w       = (const float*)d_in[6];
    const int*   i_src     = (const int*)d_in[7];
    const int*   i_dst     = (const int*)d_in[8];
    const float* i_w       = (const float*)d_in[9];
    const float* W_fu      = (const float*)d_in[10];
    const float* b_fu      = (const float*)d_in[11];
    const float* W_fi      = (const float*)d_in[12];
    const float* b_fi      = (const float*)d_in[13];
    const float* W_uc      = (const float*)d_in[14];
    const float* W_ic      = (const float*)d_in[15];
    const float* bn_fu     = (const float*)d_in[16];
    const float* bn_hu     = (const float*)d_in[17];
    const float* bn_fi     = (const float*)d_in[18];
    const float* bn_hi     = (const float*)d_in[19];
    const float* W2_fu     = (const float*)d_in[20];
    const float* W2_hu     = (const float*)d_in[21];
    const float* W2_fi     = (const float*)d_in[22];
    const float* W2_hi     = (const float*)d_in[23];
    const float* Wdec      = (const float*)d_in[24];
    const float* Wcomb     = (const float*)d_in[25];
    float* out = (float*)d_out;

    void* p;
    cudaGetSymbolAddress(&p, g_agg); float* agg  = (float*)p;
    cudaGetSymbolAddress(&p, g_f);   float* fb   = (float*)p;
    cudaGetSymbolAddress(&p, g_h);   float* hb   = (float*)p;
    cudaGetSymbolAddress(&p, g_emb); float* emb  = (float*)p;
    cudaGetSymbolAddress(&p, g_t);   float* tdec = (float*)p;

    // 1) hist + tofp16 fused (g_cnt starts zero: module load / decode tail)
    prep_kernel<<<HISTBLK + FP16BLK, 256>>>(nullptr, u_dst, i_dst, user_feat, item_feat);
    scan_kernel<<<SEGS, 1024>>>();
    scatter_kernel<<<HISTBLK, 256>>>(u_src, u_dst, u_w, i_src, i_dst, i_w);

    // 2) aggregation + f projections fused
    aggproj_kernel<<<dim3(BATCH, SEGS + 1), 128>>>(
        user_feat, item_feat, user_idx, item_idx,
        W_fu, b_fu, bn_fu, W_fi, b_fi, bn_fi, fb);

    // 3) class projections
    class_proj_kernel<<<dim3(1, 64, 10), 128>>>(agg, W_uc, W_ic, bn_hu, bn_hi, hb);

    // 4) embeddings
    emb_kernel<<<dim3(2, 64, 2), 128>>>(fb, hb, W2_fu, W2_hu, W2_fi, W2_hi, emb);

    // 5) bilinear decoder
    float* uemb = emb;
    float* iemb = emb + (long)BATCH * D_EMB;
    dec_kernel<<<dim3(2, 64, 2), 128>>>(uemb, Wdec, tdec);
    decode_kernel<<<BATCH, 256>>>(tdec, tdec + (long)BATCH * D_EMB, iemb, Wcomb, out);
}

// round 16
// speedup vs baseline: 2.1148x; 2.1148x over previous
#include <cuda_runtime.h>
#include <cuda_fp16.h>
#include <cuda_bf16.h>
#include <mma.h>
#include <cstdint>

using namespace nvcuda;

#define N_USERS  100000
#define N_ITEMS  100000
#define N_FEAT   256
#define BATCH    8192
#define CLASSES  5
#define EDGES    500000
#define D_CONV   128
#define D_EMB    256
#define SEGS     10
#define BN_EPS   1e-3f

#define ASTRIDE_H 24   // A smem row stride in halves
#define BSTRIDE_H 136  // B smem row stride in halves
#define CSTRIDE   20   // staging row stride (floats)

// ---------------- scratch ----------------------------------------------------
__device__ int    g_cnt [SEGS * BATCH];   // zero at load; re-zeroed by decode tail
__device__ int    g_off [SEGS * BATCH];
__device__ int2   g_ep  [SEGS * EDGES];
__device__ __half g_u16 [(long)N_USERS * N_FEAT];
__device__ __half g_i16 [(long)N_ITEMS * N_FEAT];
__device__ float  g_agg [SEGS * BATCH * N_FEAT];
__device__ float  g_f   [2 * BATCH * N_FEAT];
__device__ float  g_h   [2 * BATCH * CLASSES * D_CONV];
__device__ float  g_emb [2 * BATCH * D_EMB];
__device__ float  g_t   [2 * BATCH * D_EMB];

#define EQUARTER   (SEGS * EDGES / 4)            // 1,250,000
#define HISTBLK    ((EQUARTER + 255) / 256)      // 4883
#define FP16QUADS  (2L * N_USERS * N_FEAT / 4)   // 12.8M
#define FP16BLK    ((int)((FP16QUADS + 255) / 256))

// ---------------- prep: hist (blocks [0,HISTBLK)) + tofp16 (rest) -----------
__global__ void prep_kernel(const int* __restrict__ udst, const int* __restrict__ idst,
                            const float* __restrict__ uf, const float* __restrict__ itf) {
    int b = blockIdx.x;
    if (b < HISTBLK) {
        int i = b * 256 + threadIdx.x;
        if (i >= EQUARTER) return;
#pragma unroll
        for (int j = 0; j < 4; j++) {
            int idx = i + j * EQUARTER;
            int seg = idx / EDGES, e = idx - seg * EDGES;
            int dst = (seg < CLASSES) ? udst[seg * EDGES + e]
                                      : idst[(seg - CLASSES) * EDGES + e];
            atomicAdd(&g_cnt[seg * BATCH + dst], 1);
        }
    } else {
        long i = (long)(b - HISTBLK) * 256 + threadIdx.x;
        const long Q = (long)N_USERS * N_FEAT / 4;
        if (i < Q) {
            float4 v = ((const float4*)uf)[i];
            __half2* o = (__half2*)g_u16;
            o[i * 2]     = __floats2half2_rn(v.x, v.y);
            o[i * 2 + 1] = __floats2half2_rn(v.z, v.w);
        } else if (i < 2 * Q) {
            long j = i - Q;
            float4 v = ((const float4*)itf)[j];
            __half2* o = (__half2*)g_i16;
            o[j * 2]     = __floats2half2_rn(v.x, v.y);
            o[j * 2 + 1] = __floats2half2_rn(v.z, v.w);
        }
    }
}

__global__ void scan_kernel() {
    int seg = blockIdx.x;
    int t = threadIdx.x;
    int base = seg * BATCH + t * 8;
    int v[8], s = 0;
#pragma unroll
    for (int j = 0; j < 8; j++) { v[j] = g_cnt[base + j]; s += v[j]; }
    __shared__ int sh[1024];
    sh[t] = s;
    __syncthreads();
    for (int off = 1; off < 1024; off <<= 1) {
        int x = (t >= off) ? sh[t - off] : 0;
        __syncthreads();
        sh[t] += x;
        __syncthreads();
    }
    int run = sh[t] - s;
#pragma unroll
    for (int j = 0; j < 8; j++) {
        g_off[base + j] = run;
        g_cnt[base + j] = run;
        run += v[j];
    }
}

__global__ void scatter_kernel(const int* __restrict__ usrc, const int* __restrict__ udst,
                               const float* __restrict__ uw,
                               const int* __restrict__ isrc, const int* __restrict__ idst,
                               const float* __restrict__ iw) {
    int i = blockIdx.x * 256 + threadIdx.x;
    if (i >= EQUARTER) return;
#pragma unroll
    for (int j = 0; j < 4; j++) {
        int idx = i + j * EQUARTER;
        int seg = idx / EDGES, e = idx - seg * EDGES;
        int src, dst; float w;
        if (seg < CLASSES) {
            int o = seg * EDGES + e;
            src = usrc[o]; dst = udst[o]; w = uw[o];
        } else {
            int o = (seg - CLASSES) * EDGES + e;
            src = isrc[o]; dst = idst[o]; w = iw[o];
        }
        int pos = atomicAdd(&g_cnt[seg * BATCH + dst], 1);
        g_ep[seg * EDGES + pos] = make_int2(src, __float_as_int(w));
    }
}

// ---------------- aggregation: fp16 gather, 256 thr, 8 edge slots -----------
__global__ void agg_kernel() {
    int dst = blockIdx.x;
    int seg = blockIdx.y;
    int tid  = threadIdx.x;
    int lane = tid & 31;
    int slot = tid >> 5;
    const uint4* feat = (const uint4*)((seg < CLASSES) ? g_i16 : g_u16);
    int start = g_off[seg * BATCH + dst];
    int end   = g_cnt[seg * BATCH + dst];
    const int2* ep = g_ep + seg * EDGES;

    float acc[8];
#pragma unroll
    for (int j = 0; j < 8; j++) acc[j] = 0.f;

    for (int e = start + slot; e < end; e += 8) {
        int2 p = ep[e];
        float w = __int_as_float(p.y);
        uint4 v = feat[(long)p.x * 32 + lane];
        const __half2* h = (const __half2*)&v;
#pragma unroll
        for (int q = 0; q < 4; q++) {
            float2 f = __half22float2(h[q]);
            acc[q * 2]     += w * f.x;
            acc[q * 2 + 1] += w * f.y;
        }
    }

    __shared__ float red[256][8];
#pragma unroll
    for (int j = 0; j < 8; j++) red[tid][j] = acc[j];
    __syncthreads();
    if (slot == 0) {
        float s[8];
#pragma unroll
        for (int j = 0; j < 8; j++) s[j] = red[lane][j];
#pragma unroll
        for (int k = 1; k < 8; k++)
#pragma unroll
            for (int j = 0; j < 8; j++) s[j] += red[k * 32 + lane][j];
        float4* outp = (float4*)(g_agg + ((long)seg * BATCH + dst) * N_FEAT + lane * 8);
        outp[0] = make_float4(s[0], s[1], s[2], s[3]);
        outp[1] = make_float4(s[4], s[5], s[6], s[7]);
    }
}

// ---------------- fp16 WMMA GEMM core: 128 threads, 128x128 tile ------------
// EPI: 0 = none (direct), 1 = bias+BN+relu, 2 = BN+relu, 3 = relu (direct)
template<int EPI>
__device__ __forceinline__ void gemm_core128(
    __half (&As)[2][128][ASTRIDE_H], __half (&Bs)[2][16][BSTRIDE_H],
    float (&stage)[4][16][CSTRIDE],
    int bx, int by,
    const float* __restrict__ A1, const float* __restrict__ A2,
    int lda1, int lda2, int ksplit, const int* __restrict__ gidx,
    const float* __restrict__ B1, const float* __restrict__ B2, int ldb,
    float* __restrict__ C, int ldc, int col0, int K,
    const float* __restrict__ bias, const float* __restrict__ bnp, int bn_dim)
{
    const int tid = threadIdx.x;
    const int m0 = by * 128, n0 = bx * 128;
    const int warp = tid >> 5, lane = tid & 31;
    const int wm0 = (warp & 1) * 64, wn0 = (warp >> 1) * 64;

    const int arow = tid;
    const int brow = tid >> 3, bcol = (tid & 7) * 16;

    const float *Ap1, *Ap2 = nullptr;
    {
        int r = gidx ? gidx[m0 + arow] : (m0 + arow);
        Ap1 = A1 + (long)r * lda1;
        if (A2) Ap2 = A2 + (long)r * lda2;
    }
    const float* Bp1 = B1 + n0 + bcol;
    const float* Bp2 = B2 ? (B2 + n0 + bcol) : nullptr;

    wmma::fragment<wmma::accumulator, 16, 16, 16, float> facc[4][4];
#pragma unroll
    for (int i = 0; i < 4; i++)
#pragma unroll
        for (int j = 0; j < 4; j++) wmma::fill_fragment(facc[i][j], 0.f);

    float a_st[16], b_st[16];

    auto load_chunk = [&](int k0) {
        const float *ap, *bp;
        if (k0 < ksplit) {
            ap = Ap1 + k0;
            bp = Bp1 + (long)(k0 + brow) * ldb;
        } else {
            ap = Ap2 + (k0 - ksplit);
            bp = Bp2 + (long)(k0 - ksplit + brow) * ldb;
        }
#pragma unroll
        for (int q = 0; q < 4; q++) {
            float4 x = *(const float4*)(ap + q * 4);
            a_st[q * 4 + 0] = x.x; a_st[q * 4 + 1] = x.y;
            a_st[q * 4 + 2] = x.z; a_st[q * 4 + 3] = x.w;
        }
#pragma unroll
        for (int q = 0; q < 4; q++) {
            float4 u = *(const float4*)(bp + q * 4);
            b_st[q * 4 + 0] = u.x; b_st[q * 4 + 1] = u.y;
            b_st[q * 4 + 2] = u.z; b_st[q * 4 + 3] = u.w;
        }
    };

    auto store_chunk = [&](int buf) {
        __half2 ha[8];
#pragma unroll
        for (int q = 0; q < 8; q++)
            ha[q] = __floats2half2_rn(a_st[q * 2], a_st[q * 2 + 1]);
        *(uint4*)&As[buf][arow][0] = *(uint4*)&ha[0];
        *(uint4*)&As[buf][arow][8] = *(uint4*)&ha[4];
        __half2 hb[8];
#pragma unroll
        for (int q = 0; q < 8; q++)
            hb[q] = __floats2half2_rn(b_st[q * 2], b_st[q * 2 + 1]);
        *(uint4*)&Bs[buf][brow][bcol]     = *(uint4*)&hb[0];
        *(uint4*)&Bs[buf][brow][bcol + 8] = *(uint4*)&hb[4];
    };

    const int nc = K / 16;
    load_chunk(0);
    store_chunk(0);
    __syncthreads();

    for (int ch = 0; ch < nc; ch++) {
        int cur = ch & 1;
        if (ch + 1 < nc) load_chunk((ch + 1) * 16);
        wmma::fragment<wmma::matrix_b, 16, 16, 16, __half, wmma::row_major> fb[4];
#pragma unroll
        for (int na = 0; na < 4; na++)
            wmma::load_matrix_sync(fb[na], &Bs[cur][0][wn0 + na * 16], BSTRIDE_H);
#pragma unroll
        for (int ma = 0; ma < 4; ma++) {
            wmma::fragment<wmma::matrix_a, 16, 16, 16, __half, wmma::row_major> fa;
            wmma::load_matrix_sync(fa, &As[cur][wm0 + ma * 16][0], ASTRIDE_H);
#pragma unroll
            for (int na = 0; na < 4; na++)
                wmma::mma_sync(facc[ma][na], fa, fb[na], facc[ma][na]);
        }
        if (ch + 1 < nc) {
            store_chunk(cur ^ 1);
            __syncthreads();
        }
    }

    if (EPI == 0 || EPI == 3) {
#pragma unroll
        for (int ma = 0; ma < 4; ma++)
#pragma unroll
            for (int na = 0; na < 4; na++) {
                if (EPI == 3) {
#pragma unroll
                    for (int e = 0; e < facc[ma][na].num_elements; e++)
                        facc[ma][na].x[e] = fmaxf(facc[ma][na].x[e], 0.f);
                }
                float* cp = C + (long)(m0 + wm0 + ma * 16) * ldc
                              + col0 + n0 + wn0 + na * 16;
                wmma::store_matrix_sync(cp, facc[ma][na], ldc, wmma::mem_row_major);
            }
    } else {
        __syncthreads();
        const int srow = lane >> 1;
        const int scol = (lane & 1) * 8;
#pragma unroll
        for (int ma = 0; ma < 4; ma++) {
#pragma unroll
            for (int na = 0; na < 4; na++) {
                wmma::store_matrix_sync(&stage[warp][0][0], facc[ma][na], CSTRIDE,
                                        wmma::mem_row_major);
                __syncwarp();
                int r  = m0 + wm0 + ma * 16 + srow;
                int cb = n0 + wn0 + na * 16 + scol;
                float x[8];
#pragma unroll
                for (int j = 0; j < 8; j++) {
                    float v = stage[warp][srow][scol + j];
                    int cgl = cb + j;
                    int cg  = col0 + cgl;
                    if (EPI == 1) v += bias[cgl];
                    float gm = bnp[cg];
                    float be = bnp[bn_dim + cg];
                    float mn = bnp[2 * bn_dim + cg];
                    float vr = bnp[3 * bn_dim + cg];
                    v = gm * (v - mn) * rsqrtf(vr + BN_EPS) + be;
                    x[j] = fmaxf(v, 0.f);
                }
                float* cp = C + (long)r * ldc + col0 + cb;
                *(float4*)(cp)     = make_float4(x[0], x[1], x[2], x[3]);
                *(float4*)(cp + 4) = make_float4(x[4], x[5], x[6], x[7]);
                __syncwarp();
            }
        }
    }
}

// ---- f projections (z=0,1) + class projections (z=2..11), one launch -------
__global__ void __launch_bounds__(128) proj_batch_kernel(
    const float* __restrict__ user_feat, const float* __restrict__ item_feat,
    const int* __restrict__ user_idx, const int* __restrict__ item_idx,
    const float* __restrict__ W_fu, const float* __restrict__ b_fu, const float* __restrict__ bn_fu,
    const float* __restrict__ W_fi, const float* __restrict__ b_fi, const float* __restrict__ bn_fi,
    const float* __restrict__ agg,
    const float* __restrict__ Wuc, const float* __restrict__ Wic,
    const float* __restrict__ bn_hu, const float* __restrict__ bn_hi,
    float* __restrict__ fb, float* __restrict__ hb)
{
    __shared__ __half As[2][128][ASTRIDE_H];
    __shared__ __half Bs[2][16][BSTRIDE_H];
    __shared__ float  St[4][16][CSTRIDE];
    int z = blockIdx.z;
    if (z < 2) {
        const float* A   = z ? item_feat : user_feat;
        const int*   gx  = z ? item_idx  : user_idx;
        const float* B   = z ? W_fi  : W_fu;
        const float* bi  = z ? b_fi  : b_fu;
        const float* bn  = z ? bn_fi : bn_fu;
        float* C = fb + (long)z * BATCH * 256;
        gemm_core128<1>(As, Bs, St, blockIdx.x, blockIdx.y, A, nullptr, N_FEAT, 0, 1 << 30, gx,
                        B, nullptr, 256, C, 256, 0, N_FEAT, bi, bn, 256);
    } else {
        if (blockIdx.x) return;   // class proj is N=128
        int seg = z - 2;
        int side = seg / CLASSES, c = seg % CLASSES;
        const float* A  = agg + (long)seg * BATCH * N_FEAT;
        const float* B  = (side ? Wic : Wuc) + (long)c * N_FEAT * D_CONV;
        const float* bn = side ? bn_hi : bn_hu;
        float* C = hb + (long)side * BATCH * (CLASSES * D_CONV);
        gemm_core128<2>(As, Bs, St, 0, blockIdx.y, A, nullptr, N_FEAT, 0, 1 << 30, nullptr,
                        B, nullptr, D_CONV, C, CLASSES * D_CONV, c * D_CONV,
                        N_FEAT, nullptr, bn, CLASSES * D_CONV);
    }
}

// ---- embeddings --------------------------------------------------------------
__global__ void __launch_bounds__(128) emb_kernel(
    const float* __restrict__ fb, const float* __restrict__ hb,
    const float* __restrict__ W2_fu, const float* __restrict__ W2_hu,
    const float* __restrict__ W2_fi, const float* __restrict__ W2_hi,
    float* __restrict__ emb)
{
    __shared__ __half As[2][128][ASTRIDE_H];
    __shared__ __half Bs[2][16][BSTRIDE_H];
    __shared__ float  St[4][16][CSTRIDE];
    const int HD = CLASSES * D_CONV;
    int z = blockIdx.z;
    const float* A1 = fb + (long)z * BATCH * 256;
    const float* A2 = hb + (long)z * BATCH * HD;
    const float* B1 = z ? W2_fi : W2_fu;
    const float* B2 = z ? W2_hi : W2_hu;
    float* C = emb + (long)z * BATCH * D_EMB;
    gemm_core128<3>(As, Bs, St, blockIdx.x, blockIdx.y, A1, A2, 256, HD, 256, nullptr,
                    B1, B2, D_EMB, C, D_EMB, 0, 256 + HD, nullptr, nullptr, 0);
}

// ---- decoder t_k = user_emb @ Wdec[k] ---------------------------------------
__global__ void __launch_bounds__(128) dec_kernel(
    const float* __restrict__ uemb, const float* __restrict__ Wdec,
    float* __restrict__ tdec)
{
    __shared__ __half As[2][128][ASTRIDE_H];
    __shared__ __half Bs[2][16][BSTRIDE_H];
    __shared__ float  St[4][16][CSTRIDE];
    int z = blockIdx.z;
    gemm_core128<0>(As, Bs, St, blockIdx.x, blockIdx.y, uemb, nullptr, D_EMB, 0, 1 << 30,
                    nullptr, Wdec + (long)z * D_EMB * D_EMB, nullptr, D_EMB,
                    tdec + (long)z * BATCH * D_EMB, D_EMB, 0, D_EMB,
                    nullptr, nullptr, 0);
}

// ---------------- bilinear combine + counter re-zero -------------------------
__global__ void decode_kernel(const float* __restrict__ t0, const float* __restrict__ t1,
                              const float* __restrict__ ve, const float* __restrict__ Wcomb,
                              float* __restrict__ out) {
    int b = blockIdx.x, t = threadIdx.x;
    float v  = ve[(long)b * D_EMB + t];
    float a0 = t0[(long)b * D_EMB + t] * v;
    float a1 = t1[(long)b * D_EMB + t] * v;
#pragma unroll
    for (int o = 16; o; o >>= 1) {
        a0 += __shfl_down_sync(0xffffffffu, a0, o);
        a1 += __shfl_down_sync(0xffffffffu, a1, o);
    }
    __shared__ float s0[8], s1[8];
    if ((t & 31) == 0) { s0[t >> 5] = a0; s1[t >> 5] = a1; }
    __syncthreads();
    if (t == 0) {
        float d0 = 0.f, d1 = 0.f;
#pragma unroll
        for (int i = 0; i < 8; i++) { d0 += s0[i]; d1 += s1[i]; }
        s0[0] = d0; s1[0] = d1;
    }
    __syncthreads();
    if (t < CLASSES)
        out[(long)b * CLASSES + t] = Wcomb[t * 2] * s0[0] + Wcomb[t * 2 + 1] * s1[0];
    // re-zero edge counters for the next call/replay (g_cnt is 0 at module load)
    if (t >= 32 && t < 32 + SEGS) g_cnt[(long)b * SEGS + (t - 32)] = 0;
}

// ---------------- launch ----------------------------------------------------
extern "C" void kernel_launch(void* const* d_in, const int* in_sizes, int n_in,
                              void* d_out, int out_size) {
    const float* user_feat = (const float*)d_in[0];
    const float* item_feat = (const float*)d_in[1];
    const int*   user_idx  = (const int*)d_in[2];
    const int*   item_idx  = (const int*)d_in[3];
    const int*   u_src     = (const int*)d_in[4];
    const int*   u_dst     = (const int*)d_in[5];
    const float* u_w       = (const float*)d_in[6];
    const int*   i_src     = (const int*)d_in[7];
    const int*   i_dst     = (const int*)d_in[8];
    const float* i_w       = (const float*)d_in[9];
    const float* W_fu      = (const float*)d_in[10];
    const float* b_fu      = (const float*)d_in[11];
    const float* W_fi      = (const float*)d_in[12];
    const float* b_fi      = (const float*)d_in[13];
    const float* W_uc      = (const float*)d_in[14];
    const float* W_ic      = (const float*)d_in[15];
    const float* bn_fu     = (const float*)d_in[16];
    const float* bn_hu     = (const float*)d_in[17];
    const float* bn_fi     = (const float*)d_in[18];
    const float* bn_hi     = (const float*)d_in[19];
    const float* W2_fu     = (const float*)d_in[20];
    const float* W2_hu     = (const float*)d_in[21];
    const float* W2_fi     = (const float*)d_in[22];
    const float* W2_hi     = (const float*)d_in[23];
    const float* Wdec      = (const float*)d_in[24];
    const float* Wcomb     = (const float*)d_in[25];
    float* out = (float*)d_out;

    void* p;
    cudaGetSymbolAddress(&p, g_agg); float* agg  = (float*)p;
    cudaGetSymbolAddress(&p, g_f);   float* fb   = (float*)p;
    cudaGetSymbolAddress(&p, g_h);   float* hb   = (float*)p;
    cudaGetSymbolAddress(&p, g_emb); float* emb  = (float*)p;
    cudaGetSymbolAddress(&p, g_t);   float* tdec = (float*)p;

    // 1) hist + tofp16 fused (g_cnt zero: module load / decode tail)
    prep_kernel<<<HISTBLK + FP16BLK, 256>>>(u_dst, i_dst, user_feat, item_feat);
    scan_kernel<<<SEGS, 1024>>>();
    scatter_kernel<<<HISTBLK, 256>>>(u_src, u_dst, u_w, i_src, i_dst, i_w);

    // 2) aggregation (dedicated high-occupancy kernel)
    agg_kernel<<<dim3(BATCH, SEGS), 256>>>();

    // 3) f projections + class projections, one launch
    proj_batch_kernel<<<dim3(2, 64, 12), 128>>>(
        user_feat, item_feat, user_idx, item_idx,
        W_fu, b_fu, bn_fu, W_fi, b_fi, bn_fi,
        agg, W_uc, W_ic, bn_hu, bn_hi, fb, hb);

    // 4) embeddings
    emb_kernel<<<dim3(2, 64, 2), 128>>>(fb, hb, W2_fu, W2_hu, W2_fi, W2_hi, emb);

    // 5) bilinear decoder
    float* uemb = emb;
    float* iemb = emb + (long)BATCH * D_EMB;
    dec_kernel<<<dim3(2, 64, 2), 128>>>(uemb, Wdec, tdec);
    decode_kernel<<<BATCH, 256>>>(tdec, tdec + (long)BATCH * D_EMB, iemb, Wcomb, out);
}